// round 1
// baseline (speedup 1.0000x reference)
#include <cuda_runtime.h>
#include <math.h>

#define BB 4
#define CC 256
#define HH 64
#define WW 64
#define NN (HH*WW)      // 4096
#define CQK 32

// ---- scratch (static device globals; no allocation) ----
__device__ float g_Q[BB*CQK*NN];          // 2 MB   [b][d][n]
__device__ float g_K[BB*CQK*NN];          // 2 MB   [b][d][n]
__device__ float g_V[BB*CC*NN];           // 16 MB  [b][c][n]
__device__ float g_S[(size_t)BB*NN*NN];   // 256 MB [b][q][k]
__device__ float g_M[BB*NN];              // column max
__device__ float g_Linv[BB*NN];           // 1/column-sum

// ============================================================
// Conv 3x3 SAME: out[b][co][y][x] = bias[co] + sum_ci,dy,dx x*w
// Tile 32x32 spatial, block (32,8), each thread 4 rows, CO_TILE=8
// ============================================================
#define CI_T 4
#define CO_T 8

__global__ void __launch_bounds__(256) conv3x3_kernel(
    const float* __restrict__ x, const float* __restrict__ w,
    const float* __restrict__ bias, float* __restrict__ out, int CO)
{
    __shared__ float xs[CI_T][34][34];
    __shared__ float ws[CO_T][CI_T][9];

    const int tx = threadIdx.x;            // 0..31
    const int ty = threadIdx.y;            // 0..7
    const int tid = ty * 32 + tx;
    const int tile_x = blockIdx.x * 32;
    const int tile_y = blockIdx.y * 32;
    const int cogs = CO / CO_T;
    const int cog = blockIdx.z % cogs;
    const int b   = blockIdx.z / cogs;
    const int co0 = cog * CO_T;

    float acc[CO_T][4];
#pragma unroll
    for (int i = 0; i < CO_T; i++)
#pragma unroll
        for (int r = 0; r < 4; r++) acc[i][r] = 0.f;

    const float* xb = x + (size_t)b * CC * HH * WW;

    for (int ci0 = 0; ci0 < CC; ci0 += CI_T) {
        // stage x patch (with halo, zero-padded at borders)
        for (int idx = tid; idx < CI_T * 34 * 34; idx += 256) {
            int ci = idx / (34 * 34);
            int rr = (idx / 34) % 34;
            int cc = idx % 34;
            int gy = tile_y + rr - 1;
            int gx = tile_x + cc - 1;
            float v = 0.f;
            if (gy >= 0 && gy < HH && gx >= 0 && gx < WW)
                v = xb[(size_t)(ci0 + ci) * HH * WW + gy * WW + gx];
            xs[ci][rr][cc] = v;
        }
        // stage weights
        for (int idx = tid; idx < CO_T * CI_T * 9; idx += 256) {
            int co = idx / (CI_T * 9);
            int rem = idx % (CI_T * 9);
            int ci = rem / 9;
            int t = rem % 9;
            ws[co][ci][t] = w[((size_t)(co0 + co) * CC + (ci0 + ci)) * 9 + t];
        }
        __syncthreads();

        const int oy = ty * 4;   // local output row base
#pragma unroll
        for (int ci = 0; ci < CI_T; ci++) {
            float xv[6][3];
#pragma unroll
            for (int rr = 0; rr < 6; rr++)
#pragma unroll
                for (int c2 = 0; c2 < 3; c2++)
                    xv[rr][c2] = xs[ci][oy + rr][tx + c2];
#pragma unroll
            for (int co = 0; co < CO_T; co++) {
#pragma unroll
                for (int t = 0; t < 9; t++) {
                    const int dy = t / 3, dx = t % 3;
                    const float wv = ws[co][ci][t];
#pragma unroll
                    for (int r = 0; r < 4; r++)
                        acc[co][r] = fmaf(xv[r + dy][dx], wv, acc[co][r]);
                }
            }
        }
        __syncthreads();
    }

#pragma unroll
    for (int co = 0; co < CO_T; co++) {
        const float bv = bias[co0 + co];
#pragma unroll
        for (int r = 0; r < 4; r++) {
            const int gy = tile_y + ty * 4 + r;
            const int gx = tile_x + tx;
            out[((size_t)b * CO + co0 + co) * HH * WW + gy * WW + gx] = acc[co][r] + bv;
        }
    }
}

// ============================================================
// S[b][q][k] = sum_d Q[b][d][q] * K[b][d][k]
// 64x64 tile, K-dim = 32 fully staged; 4x4 microtile, float4 LDS
// ============================================================
__global__ void __launch_bounds__(256) qk_kernel()
{
    __shared__ float Qs[CQK][68];
    __shared__ float Ks[CQK][68];
    const int tid = threadIdx.x;
    const int q0 = blockIdx.x * 64;
    const int k0 = blockIdx.y * 64;
    const int b = blockIdx.z;

    const float* Qg = g_Q + (size_t)b * CQK * NN;
    const float* Kg = g_K + (size_t)b * CQK * NN;

    for (int idx = tid; idx < CQK * 64; idx += 256) {
        const int d = idx >> 6;
        const int j = idx & 63;
        Qs[d][j] = Qg[d * NN + q0 + j];
        Ks[d][j] = Kg[d * NN + k0 + j];
    }
    __syncthreads();

    const int kt = tid & 15;
    const int qt = tid >> 4;
    float acc[4][4] = {};
#pragma unroll
    for (int d = 0; d < CQK; d++) {
        const float4 a = *(const float4*)&Qs[d][qt * 4];
        const float4 bb = *(const float4*)&Ks[d][kt * 4];
        const float av[4] = {a.x, a.y, a.z, a.w};
        const float bv[4] = {bb.x, bb.y, bb.z, bb.w};
#pragma unroll
        for (int i = 0; i < 4; i++)
#pragma unroll
            for (int j = 0; j < 4; j++)
                acc[i][j] = fmaf(av[i], bv[j], acc[i][j]);
    }

    float* Sb = g_S + (size_t)b * NN * NN;
#pragma unroll
    for (int i = 0; i < 4; i++) {
        const int q = q0 + qt * 4 + i;
        float4 o;
        o.x = acc[i][0]; o.y = acc[i][1]; o.z = acc[i][2]; o.w = acc[i][3];
        *(float4*)&Sb[(size_t)q * NN + k0 + kt * 4] = o;
    }
}

// ============================================================
// Column softmax stats over q (axis=-2): M[k], 1/L[k]
// coalesced: consecutive threads -> consecutive k
// ============================================================
__global__ void __launch_bounds__(256) colstats_kernel()
{
    const int b = blockIdx.y;
    const int k = blockIdx.x * 256 + threadIdx.x;
    const float* Sb = g_S + (size_t)b * NN * NN;

    float m = -3.0e38f;
    float l = 0.f;
    for (int q = 0; q < NN; q += 4) {
        const float v0 = Sb[(size_t)(q + 0) * NN + k];
        const float v1 = Sb[(size_t)(q + 1) * NN + k];
        const float v2 = Sb[(size_t)(q + 2) * NN + k];
        const float v3 = Sb[(size_t)(q + 3) * NN + k];
        const float mm = fmaxf(fmaxf(v0, v1), fmaxf(v2, v3));
        if (mm > m) { l *= __expf(m - mm); m = mm; }
        l += __expf(v0 - m) + __expf(v1 - m) + __expf(v2 - m) + __expf(v3 - m);
    }
    g_M[b * NN + k] = m;
    g_Linv[b * NN + k] = 1.f / l;
}

// ============================================================
// out[b][c][k] = x[b][c][k] + gamma * Linv[k] *
//                sum_q V[b][c][q] * exp(S[b][q][k] - M[k])
// 64c x 64k tile, q-chunks of 32, exp fused into P staging
// ============================================================
__global__ void __launch_bounds__(256) ov_kernel(
    const float* __restrict__ x, const float* __restrict__ gamma,
    float* __restrict__ out)
{
    __shared__ float Vs[32][68];   // Vs[q][c]
    __shared__ float Ps[32][68];   // Ps[q][k] = exp(S - M)
    __shared__ float Ms[64], Ls[64];

    const int tid = threadIdx.x;
    const int k0 = blockIdx.x * 64;
    const int c0 = blockIdx.y * 64;
    const int b = blockIdx.z;

    if (tid < 64) {
        Ms[tid] = g_M[b * NN + k0 + tid];
        Ls[tid] = g_Linv[b * NN + k0 + tid];
    }

    const float* Vg = g_V + ((size_t)b * CC + c0) * NN;
    const float* Sb = g_S + (size_t)b * NN * NN;

    const int kt = tid & 15;       // k micro index
    const int ct = tid >> 4;       // c micro index
    const int lq = tid & 31;       // V loader: q lane
    const int lc = tid >> 5;       // V loader: c row (8 per pass)
    const int lk = tid & 63;       // P loader: k lane
    const int lq2 = tid >> 6;      // P loader: q row (4 per pass)

    float acc[4][4] = {};
    __syncthreads();               // Ms/Ls visible

    for (int qc = 0; qc < NN; qc += 32) {
        // stage V (transposed into Vs[q][c])
#pragma unroll
        for (int p = 0; p < 8; p++) {
            const int c = lc + p * 8;
            Vs[lq][c] = Vg[(size_t)c * NN + qc + lq];
        }
        // stage P = exp(S - M)
#pragma unroll
        for (int p = 0; p < 8; p++) {
            const int q = lq2 + p * 4;
            const float s = Sb[(size_t)(qc + q) * NN + k0 + lk];
            Ps[q][lk] = __expf(s - Ms[lk]);
        }
        __syncthreads();

#pragma unroll
        for (int q = 0; q < 32; q++) {
            const float4 a = *(const float4*)&Vs[q][ct * 4];
            const float4 bb = *(const float4*)&Ps[q][kt * 4];
            const float av[4] = {a.x, a.y, a.z, a.w};
            const float bv[4] = {bb.x, bb.y, bb.z, bb.w};
#pragma unroll
            for (int i = 0; i < 4; i++)
#pragma unroll
                for (int j = 0; j < 4; j++)
                    acc[i][j] = fmaf(av[i], bv[j], acc[i][j]);
        }
        __syncthreads();
    }

    const float g = gamma[0];
#pragma unroll
    for (int i = 0; i < 4; i++) {
        const int c = c0 + ct * 4 + i;
        const size_t base = ((size_t)b * CC + c) * NN + k0 + kt * 4;
        const float4 xv = *(const float4*)&x[base];
        float4 o;
        o.x = xv.x + g * acc[i][0] * Ls[kt * 4 + 0];
        o.y = xv.y + g * acc[i][1] * Ls[kt * 4 + 1];
        o.z = xv.z + g * acc[i][2] * Ls[kt * 4 + 2];
        o.w = xv.w + g * acc[i][3] * Ls[kt * 4 + 3];
        *(float4*)&out[base] = o;
    }
}

// ============================================================
extern "C" void kernel_launch(void* const* d_in, const int* in_sizes, int n_in,
                              void* d_out, int out_size)
{
    const float* x     = (const float*)d_in[0];
    const float* wq    = (const float*)d_in[1];
    const float* bq    = (const float*)d_in[2];
    const float* wk    = (const float*)d_in[3];
    const float* bk    = (const float*)d_in[4];
    const float* wv    = (const float*)d_in[5];
    const float* bv    = (const float*)d_in[6];
    const float* gamma = (const float*)d_in[7];
    float* out = (float*)d_out;

    float *Qp, *Kp, *Vp;
    cudaGetSymbolAddress((void**)&Qp, g_Q);
    cudaGetSymbolAddress((void**)&Kp, g_K);
    cudaGetSymbolAddress((void**)&Vp, g_V);

    dim3 cblk(32, 8);
    conv3x3_kernel<<<dim3(2, 2, BB * (CQK / CO_T)), cblk>>>(x, wq, bq, Qp, CQK);
    conv3x3_kernel<<<dim3(2, 2, BB * (CQK / CO_T)), cblk>>>(x, wk, bk, Kp, CQK);
    conv3x3_kernel<<<dim3(2, 2, BB * (CC  / CO_T)), cblk>>>(x, wv, bv, Vp, CC);

    qk_kernel<<<dim3(NN / 64, NN / 64, BB), 256>>>();
    colstats_kernel<<<dim3(NN / 256, BB), 256>>>();
    ov_kernel<<<dim3(NN / 64, CC / 64, BB), 256>>>(x, gamma, out);
}

// round 3
// speedup vs baseline: 1.9983x; 1.9983x over previous
#include <cuda_runtime.h>
#include <cuda_bf16.h>
#include <stdint.h>
#include <math.h>

#define BB 4
#define CC 256
#define HH 64
#define WW 64
#define NN (HH*WW)      // 4096
#define CQK 32

// ---- scratch (static device globals; no allocation) ----
__device__ float g_Q[BB*CQK*NN];          // 2 MB   [b][d][n]
__device__ float g_K[BB*CQK*NN];          // 2 MB   [b][d][n]
__device__ float g_V[BB*CC*NN];           // 16 MB  [b][c][n]
__device__ float g_S[(size_t)BB*NN*NN];   // 256 MB  S^T: [b][k][q]
__device__ float g_M[BB*NN];              // column max  (per k)
__device__ float g_Linv[BB*NN];           // 1/column-sum (per k)

// ============================================================
// helpers
// ============================================================
__device__ __forceinline__ uint32_t smem_u32(const void* p) {
    uint32_t a;
    asm("{ .reg .u64 t; cvta.to.shared.u64 t, %1; cvt.u32.u64 %0, t; }"
        : "=r"(a) : "l"(p));
    return a;
}
#define SWZ(x) ((x) ^ (((x) >> 3) & 0x70))
#define STS128U(addr, a, b, c, d) \
    asm volatile("st.shared.v4.b32 [%0], {%1, %2, %3, %4};" \
                 :: "r"(addr), "r"(a), "r"(b), "r"(c), "r"(d) : "memory")
#define LDMX4(r0, r1, r2, r3, a) \
    asm volatile("ldmatrix.sync.aligned.m8n8.x4.shared.b16 {%0,%1,%2,%3}, [%4];" \
                 : "=r"(r0), "=r"(r1), "=r"(r2), "=r"(r3) : "r"(a))
#define MMA16816(d, a0, a1, a2, a3, b0, b1) \
    asm volatile("mma.sync.aligned.m16n8k16.row.col.f32.bf16.bf16.f32 " \
                 "{%0,%1,%2,%3}, {%4,%5,%6,%7}, {%8,%9}, {%0,%1,%2,%3};" \
                 : "+f"((d)[0]), "+f"((d)[1]), "+f"((d)[2]), "+f"((d)[3]) \
                 : "r"(a0), "r"(a1), "r"(a2), "r"(a3), "r"(b0), "r"(b1))

__device__ __forceinline__ uint32_t pack_bf16(float a, float b) {
    __nv_bfloat162 h = __floats2bfloat162_rn(a, b);
    return *(uint32_t*)&h;
}

// ============================================================
// Conv 3x3 SAME: tile 32x16 spatial, block (32,8), 2 rows/thread
// ============================================================
#define CI_T 4
#define CO_T 8

__global__ void __launch_bounds__(256) conv3x3_kernel(
    const float* __restrict__ x, const float* __restrict__ w,
    const float* __restrict__ bias, float* __restrict__ out, int CO)
{
    __shared__ float xs[CI_T][18][34];
    __shared__ float ws[CO_T][CI_T][9];

    const int tx = threadIdx.x;            // 0..31
    const int ty = threadIdx.y;            // 0..7
    const int tid = ty * 32 + tx;
    const int tile_x = blockIdx.x * 32;
    const int tile_y = blockIdx.y * 16;
    const int cogs = CO / CO_T;
    const int cog = blockIdx.z % cogs;
    const int b   = blockIdx.z / cogs;
    const int co0 = cog * CO_T;

    float acc[CO_T][2];
#pragma unroll
    for (int i = 0; i < CO_T; i++) { acc[i][0] = 0.f; acc[i][1] = 0.f; }

    const float* xb = x + (size_t)b * CC * HH * WW;

    for (int ci0 = 0; ci0 < CC; ci0 += CI_T) {
        for (int idx = tid; idx < CI_T * 18 * 34; idx += 256) {
            int ci = idx / (18 * 34);
            int rr = (idx / 34) % 18;
            int cc = idx % 34;
            int gy = tile_y + rr - 1;
            int gx = tile_x + cc - 1;
            float v = 0.f;
            if (gy >= 0 && gy < HH && gx >= 0 && gx < WW)
                v = xb[(size_t)(ci0 + ci) * HH * WW + gy * WW + gx];
            xs[ci][rr][cc] = v;
        }
        for (int idx = tid; idx < CO_T * CI_T * 9; idx += 256) {
            int co = idx / (CI_T * 9);
            int rem = idx % (CI_T * 9);
            int ci = rem / 9;
            int t = rem % 9;
            ws[co][ci][t] = w[((size_t)(co0 + co) * CC + (ci0 + ci)) * 9 + t];
        }
        __syncthreads();

        const int oy = ty * 2;
#pragma unroll
        for (int ci = 0; ci < CI_T; ci++) {
            float xv[4][3];
#pragma unroll
            for (int rr = 0; rr < 4; rr++)
#pragma unroll
                for (int c2 = 0; c2 < 3; c2++)
                    xv[rr][c2] = xs[ci][oy + rr][tx + c2];
#pragma unroll
            for (int co = 0; co < CO_T; co++) {
#pragma unroll
                for (int t = 0; t < 9; t++) {
                    const int dy = t / 3, dx = t % 3;
                    const float wv = ws[co][ci][t];
                    acc[co][0] = fmaf(xv[0 + dy][dx], wv, acc[co][0]);
                    acc[co][1] = fmaf(xv[1 + dy][dx], wv, acc[co][1]);
                }
            }
        }
        __syncthreads();
    }

#pragma unroll
    for (int co = 0; co < CO_T; co++) {
        const float bv = bias[co0 + co];
#pragma unroll
        for (int r = 0; r < 2; r++) {
            const int gy = tile_y + ty * 2 + r;
            const int gx = tile_x + tx;
            out[((size_t)b * CO + co0 + co) * HH * WW + gy * WW + gx] = acc[co][r] + bv;
        }
    }
}

// ============================================================
// S^T[b][k][q] = sum_d Q[b][d][q] * K[b][d][k]
// ============================================================
__global__ void __launch_bounds__(256) qk_kernel()
{
    __shared__ float Qs[CQK][68];
    __shared__ float Ks[CQK][68];
    const int tid = threadIdx.x;
    const int q0 = blockIdx.x * 64;
    const int k0 = blockIdx.y * 64;
    const int b = blockIdx.z;

    const float* Qg = g_Q + (size_t)b * CQK * NN;
    const float* Kg = g_K + (size_t)b * CQK * NN;

    for (int idx = tid; idx < CQK * 64; idx += 256) {
        const int d = idx >> 6;
        const int j = idx & 63;
        Qs[d][j] = Qg[d * NN + q0 + j];
        Ks[d][j] = Kg[d * NN + k0 + j];
    }
    __syncthreads();

    const int kt = tid & 15;
    const int qt = tid >> 4;
    float acc[4][4] = {};
#pragma unroll
    for (int d = 0; d < CQK; d++) {
        const float4 a = *(const float4*)&Qs[d][qt * 4];
        const float4 bb = *(const float4*)&Ks[d][kt * 4];
        const float av[4] = {a.x, a.y, a.z, a.w};
        const float bv[4] = {bb.x, bb.y, bb.z, bb.w};
#pragma unroll
        for (int i = 0; i < 4; i++)
#pragma unroll
            for (int j = 0; j < 4; j++)
                acc[i][j] = fmaf(av[i], bv[j], acc[i][j]);
    }

    // transposed store: S^T[k][q], float4 over q
    float* STb = g_S + (size_t)b * NN * NN;
#pragma unroll
    for (int j = 0; j < 4; j++) {
        const int k = k0 + kt * 4 + j;
        float4 o;
        o.x = acc[0][j]; o.y = acc[1][j]; o.z = acc[2][j]; o.w = acc[3][j];
        *(float4*)&STb[(size_t)k * NN + q0 + qt * 4] = o;
    }
}

// ============================================================
// Row reduction over q of S^T: M[k], 1/L[k]. One block per (k,b).
// ============================================================
__global__ void __launch_bounds__(256) colstats_kernel()
{
    __shared__ float red[8];
    __shared__ float bcast;
    const int k = blockIdx.x;
    const int b = blockIdx.y;
    const int tid = threadIdx.x;
    const int wid = tid >> 5, lid = tid & 31;
    const float* row = g_S + (size_t)b * NN * NN + (size_t)k * NN;

    float v[16];
#pragma unroll
    for (int p = 0; p < 4; p++) {
        const float4 f = *(const float4*)&row[p * 1024 + tid * 4];
        v[p * 4 + 0] = f.x; v[p * 4 + 1] = f.y; v[p * 4 + 2] = f.z; v[p * 4 + 3] = f.w;
    }
    float m = v[0];
#pragma unroll
    for (int i = 1; i < 16; i++) m = fmaxf(m, v[i]);
#pragma unroll
    for (int o = 16; o > 0; o >>= 1)
        m = fmaxf(m, __shfl_xor_sync(0xFFFFFFFF, m, o));
    if (lid == 0) red[wid] = m;
    __syncthreads();
    if (tid == 0) {
        float mm = red[0];
#pragma unroll
        for (int i = 1; i < 8; i++) mm = fmaxf(mm, red[i]);
        bcast = mm;
    }
    __syncthreads();
    m = bcast;

    float l = 0.f;
#pragma unroll
    for (int i = 0; i < 16; i++) l += __expf(v[i] - m);
#pragma unroll
    for (int o = 16; o > 0; o >>= 1)
        l += __shfl_xor_sync(0xFFFFFFFF, l, o);
    __syncthreads();
    if (lid == 0) red[wid] = l;
    __syncthreads();
    if (tid == 0) {
        float ll = 0.f;
#pragma unroll
        for (int i = 0; i < 8; i++) ll += red[i];
        g_M[b * NN + k] = m;
        g_Linv[b * NN + k] = 1.f / ll;
    }
}

// ============================================================
// OV via mma.sync (HMMA bf16):
//   D[c,k] = sum_q V[c,q] * exp(S^T[k,q] - M[k])
//   out = x + gamma * Linv[k] * D
// Block tile: 128 c x 64 k, q-chunks of 64. 8 warps = 4(m) x 2(n).
// A = V tile [128][64] bf16, B = P tile [64][64] bf16, both q-contig
// (row.col mma + non-trans ldmatrix).
// ============================================================
#define OV_QC 64

__global__ void __launch_bounds__(256) ov_mma_kernel(
    const float* __restrict__ x, const float* __restrict__ gamma,
    float* __restrict__ out)
{
    // A: 128 rows * 128B = 16KB ; B: 64 rows * 128B = 8KB
    __shared__ uint32_t smem_raw[(16384 + 8192 + 128) / 4];
    __shared__ float Msh[64], Lsh[64];

    const int tid = threadIdx.x;
    const int wid = tid >> 5;
    const int lid = tid & 31;
    const int wm = wid >> 1;            // 0..3 : c block of 32
    const int wn = wid & 1;             // 0..1 : k block of 32
    const int k0 = blockIdx.x * 64;
    const int c0 = blockIdx.y * 128;
    const int b  = blockIdx.z;

    const uint32_t abase = (smem_u32(smem_raw) + 127) & ~127u;
    const uint32_t bbase = abase + 16384;

    if (tid < 64) {
        Msh[tid] = g_M[b * NN + k0 + tid];
        Lsh[tid] = g_Linv[b * NN + k0 + tid];
    }

    const float* Vg  = g_V + ((size_t)b * CC + c0) * NN;
    const float* STb = g_S + (size_t)b * NN * NN;

    const int jrow = tid >> 3;          // 0..31
    const int qoff = (tid & 7) * 8;     // 0..56

    float4 a_pre[4][2];
    float4 b_pre[2][2];

    // prefetch chunk 0
#pragma unroll
    for (int j = 0; j < 4; j++) {
        const float* vp = Vg + (size_t)(jrow + j * 32) * NN + qoff;
        a_pre[j][0] = *(const float4*)vp;
        a_pre[j][1] = *(const float4*)(vp + 4);
    }
#pragma unroll
    for (int p = 0; p < 2; p++) {
        const float* sp = STb + (size_t)(k0 + jrow + p * 32) * NN + qoff;
        b_pre[p][0] = *(const float4*)sp;
        b_pre[p][1] = *(const float4*)(sp + 4);
    }

    float acc[2][4][4];
#pragma unroll
    for (int mt = 0; mt < 2; mt++)
#pragma unroll
        for (int nt = 0; nt < 4; nt++)
#pragma unroll
            for (int i = 0; i < 4; i++) acc[mt][nt][i] = 0.f;

    for (int chunk = 0; chunk < NN / OV_QC; chunk++) {
        __syncthreads();   // previous mma reads done (also covers Msh on c0)

        // store A tile (bf16)
#pragma unroll
        for (int j = 0; j < 4; j++) {
            const int row = jrow + j * 32;
            const uint32_t sw = abase + SWZ((uint32_t)(row * 128 + qoff * 2));
            STS128U(sw,
                pack_bf16(a_pre[j][0].x, a_pre[j][0].y),
                pack_bf16(a_pre[j][0].z, a_pre[j][0].w),
                pack_bf16(a_pre[j][1].x, a_pre[j][1].y),
                pack_bf16(a_pre[j][1].z, a_pre[j][1].w));
        }
        // store B tile: exp(S - M) (bf16)
#pragma unroll
        for (int p = 0; p < 2; p++) {
            const int row = jrow + p * 32;
            const float m = Msh[row];
            float e[8];
            e[0] = __expf(b_pre[p][0].x - m); e[1] = __expf(b_pre[p][0].y - m);
            e[2] = __expf(b_pre[p][0].z - m); e[3] = __expf(b_pre[p][0].w - m);
            e[4] = __expf(b_pre[p][1].x - m); e[5] = __expf(b_pre[p][1].y - m);
            e[6] = __expf(b_pre[p][1].z - m); e[7] = __expf(b_pre[p][1].w - m);
            const uint32_t sw = bbase + SWZ((uint32_t)(row * 128 + qoff * 2));
            STS128U(sw, pack_bf16(e[0], e[1]), pack_bf16(e[2], e[3]),
                        pack_bf16(e[4], e[5]), pack_bf16(e[6], e[7]));
        }
        __syncthreads();

        // prefetch next chunk (overlaps with mma below)
        if (chunk + 1 < NN / OV_QC) {
            const int qc = (chunk + 1) * OV_QC;
#pragma unroll
            for (int j = 0; j < 4; j++) {
                const float* vp = Vg + (size_t)(jrow + j * 32) * NN + qc + qoff;
                a_pre[j][0] = *(const float4*)vp;
                a_pre[j][1] = *(const float4*)(vp + 4);
            }
#pragma unroll
            for (int p = 0; p < 2; p++) {
                const float* sp = STb + (size_t)(k0 + jrow + p * 32) * NN + qc + qoff;
                b_pre[p][0] = *(const float4*)sp;
                b_pre[p][1] = *(const float4*)(sp + 4);
            }
        }

        // mma over 4 k16 steps
        const int frow = lid & 15;
        const int fcb  = (lid >> 4) * 16;
#pragma unroll
        for (int qs = 0; qs < 4; qs++) {
            const int cb = qs * 32 + fcb;
            uint32_t A0[4], A1[4], B0[4], B1[4];
            LDMX4(A0[0], A0[1], A0[2], A0[3],
                  abase + SWZ((uint32_t)((wm * 32 + frow) * 128 + cb)));
            LDMX4(A1[0], A1[1], A1[2], A1[3],
                  abase + SWZ((uint32_t)((wm * 32 + 16 + frow) * 128 + cb)));
            LDMX4(B0[0], B0[1], B0[2], B0[3],
                  bbase + SWZ((uint32_t)((wn * 32 + frow) * 128 + cb)));
            LDMX4(B1[0], B1[1], B1[2], B1[3],
                  bbase + SWZ((uint32_t)((wn * 32 + 16 + frow) * 128 + cb)));

            MMA16816(acc[0][0], A0[0], A0[1], A0[2], A0[3], B0[0], B0[2]);
            MMA16816(acc[0][1], A0[0], A0[1], A0[2], A0[3], B0[1], B0[3]);
            MMA16816(acc[0][2], A0[0], A0[1], A0[2], A0[3], B1[0], B1[2]);
            MMA16816(acc[0][3], A0[0], A0[1], A0[2], A0[3], B1[1], B1[3]);
            MMA16816(acc[1][0], A1[0], A1[1], A1[2], A1[3], B0[0], B0[2]);
            MMA16816(acc[1][1], A1[0], A1[1], A1[2], A1[3], B0[1], B0[3]);
            MMA16816(acc[1][2], A1[0], A1[1], A1[2], A1[3], B1[0], B1[2]);
            MMA16816(acc[1][3], A1[0], A1[1], A1[2], A1[3], B1[1], B1[3]);
        }
    }

    // epilogue: out = x + g * Linv[k] * D
    const float g = gamma[0];
    const int er = lid >> 2;
    const int ec = (lid & 3) * 2;
#pragma unroll
    for (int mt = 0; mt < 2; mt++) {
#pragma unroll
        for (int nt = 0; nt < 4; nt++) {
            const int kk = wn * 32 + nt * 8 + ec;
            const float l0 = Lsh[kk], l1 = Lsh[kk + 1];
#pragma unroll
            for (int h = 0; h < 2; h++) {
                const int c = c0 + wm * 32 + mt * 16 + er + h * 8;
                const size_t idx = ((size_t)b * CC + c) * NN + k0 + kk;
                const float2 xv = *(const float2*)&x[idx];
                float2 o;
                o.x = xv.x + g * l0 * acc[mt][nt][h * 2 + 0];
                o.y = xv.y + g * l1 * acc[mt][nt][h * 2 + 1];
                *(float2*)&out[idx] = o;
            }
        }
    }
}

// ============================================================
extern "C" void kernel_launch(void* const* d_in, const int* in_sizes, int n_in,
                              void* d_out, int out_size)
{
    const float* x     = (const float*)d_in[0];
    const float* wq    = (const float*)d_in[1];
    const float* bq    = (const float*)d_in[2];
    const float* wk    = (const float*)d_in[3];
    const float* bk    = (const float*)d_in[4];
    const float* wv    = (const float*)d_in[5];
    const float* bv    = (const float*)d_in[6];
    const float* gamma = (const float*)d_in[7];
    float* out = (float*)d_out;

    float *Qp, *Kp, *Vp;
    cudaGetSymbolAddress((void**)&Qp, g_Q);
    cudaGetSymbolAddress((void**)&Kp, g_K);
    cudaGetSymbolAddress((void**)&Vp, g_V);

    dim3 cblk(32, 8);
    conv3x3_kernel<<<dim3(2, 4, BB * (CQK / CO_T)), cblk>>>(x, wq, bq, Qp, CQK);
    conv3x3_kernel<<<dim3(2, 4, BB * (CQK / CO_T)), cblk>>>(x, wk, bk, Kp, CQK);
    conv3x3_kernel<<<dim3(2, 4, BB * (CC  / CO_T)), cblk>>>(x, wv, bv, Vp, CC);

    qk_kernel<<<dim3(NN / 64, NN / 64, BB), 256>>>();
    colstats_kernel<<<dim3(NN, BB), 256>>>();
    ov_mma_kernel<<<dim3(NN / 64, CC / 128, BB), 256>>>(x, gamma, out);
}